// round 6
// baseline (speedup 1.0000x reference)
#include <cuda_runtime.h>
#include <cstdint>

#define BB 4
#define HH 16
#define SS_ 2048
#define DD 64
#define BQ 128
#define BK 64
#define NKT (SS_/BK)     /* 32 */
#define NBH (BB*HH)      /* 64 */
#define NT 128           /* 4 warps, each owns 32 q-rows */
#define VSTR 72          /* V float stride (PV loads conflict-free) */
#define KSTRW 36         /* K bf16 stride in uint32 */
#define SSTR 68          /* S float stride */

__device__ float    g_vsum[NBH*DD];
__device__ uint32_t g_mbits[SS_*(SS_/32)];

// ---------------- helpers ----------------
__device__ __forceinline__ uint32_t to_tf32(float f) {
    uint32_t r; asm("cvt.rn.tf32.f32 %0, %1;" : "=r"(r) : "f"(f)); return r;
}
__device__ __forceinline__ uint32_t bf2(float lo, float hi) {
    uint32_t r; asm("cvt.rn.bf16x2.f32 %0, %1, %2;" : "=r"(r) : "f"(hi), "f"(lo));
    return r;
}
__device__ __forceinline__ void mma8(float* d, const uint32_t* a,
                                     uint32_t b0, uint32_t b1) {
    asm volatile(
        "mma.sync.aligned.m16n8k8.row.col.f32.tf32.tf32.f32 "
        "{%0,%1,%2,%3}, {%4,%5,%6,%7}, {%8,%9}, {%0,%1,%2,%3};"
        : "+f"(d[0]), "+f"(d[1]), "+f"(d[2]), "+f"(d[3])
        : "r"(a[0]), "r"(a[1]), "r"(a[2]), "r"(a[3]), "r"(b0), "r"(b1));
}
__device__ __forceinline__ void mma16bf(float* d, const uint32_t* a,
                                        uint32_t b0, uint32_t b1) {
    asm volatile(
        "mma.sync.aligned.m16n8k16.row.col.f32.bf16.bf16.f32 "
        "{%0,%1,%2,%3}, {%4,%5,%6,%7}, {%8,%9}, {%0,%1,%2,%3};"
        : "+f"(d[0]), "+f"(d[1]), "+f"(d[2]), "+f"(d[3])
        : "r"(a[0]), "r"(a[1]), "r"(a[2]), "r"(a[3]), "r"(b0), "r"(b1));
}
__device__ __forceinline__ uint32_t mbit(uint2 mw, int k) {
    return ((k < 32 ? (mw.x >> k) : (mw.y >> (k - 32))) & 1u);
}

// ---------------------------------------------------------------------------
// pre-kernels
// ---------------------------------------------------------------------------
__global__ void vsum_kernel(const float* __restrict__ v) {
    int bh = blockIdx.x, tid = threadIdx.x;
    int d = tid & 63, strip = tid >> 6;
    const float* vp = v + (size_t)bh*SS_*DD;
    float a0 = 0.f, a1 = 0.f, a2 = 0.f, a3 = 0.f;
    for (int k = strip; k < SS_; k += 16) {
        a0 += vp[(k     )*DD + d];
        a1 += vp[(k +  4)*DD + d];
        a2 += vp[(k +  8)*DD + d];
        a3 += vp[(k + 12)*DD + d];
    }
    __shared__ float red[4][64];
    red[strip][d] = (a0 + a1) + (a2 + a3);
    __syncthreads();
    if (strip == 0)
        g_vsum[bh*DD + d] = red[0][d] + red[1][d] + red[2][d] + red[3][d];
}

__global__ void maskpack_kernel(const int* __restrict__ m) {
    int base = blockIdx.x*1024 + threadIdx.x;
    int a = m[base], b = m[base+256], c = m[base+512], d = m[base+768];
    unsigned ba = __ballot_sync(~0u, a != 0);
    unsigned bb = __ballot_sync(~0u, b != 0);
    unsigned bc = __ballot_sync(~0u, c != 0);
    unsigned bd = __ballot_sync(~0u, d != 0);
    if ((threadIdx.x & 31) == 0) {
        g_mbits[(base      ) >> 5] = ba;
        g_mbits[(base + 256) >> 5] = bb;
        g_mbits[(base + 512) >> 5] = bc;
        g_mbits[(base + 768) >> 5] = bd;
    }
}

// ---------------------------------------------------------------------------
// main attention kernel — 4 warps x 32 q-rows
// ---------------------------------------------------------------------------
__global__ void __launch_bounds__(NT, 2)
attn_kernel(const float* __restrict__ gq, const float* __restrict__ gk,
            const float* __restrict__ gv, float* __restrict__ gout)
{
    extern __shared__ float sm[];
    uint32_t* Vsu = (uint32_t*)sm;                 // [64][VSTR]  tf32
    uint32_t* Khu = (uint32_t*)(sm + 64*VSTR);     // [64][KSTRW] bf16x2
    float*    Sst = sm + 64*VSTR + 64*KSTRW;       // [128][SSTR] fp32 scores
    __shared__ float vs_s[64];

    const int tid = threadIdx.x;
    const int w   = tid >> 5;            // warp 0..3: q rows [32w, 32w+32)
    const int lane = tid & 31;
    const int g = lane >> 2;
    const int t = lane & 3;
    const int bid = blockIdx.x;
    const int bh  = bid >> 4;
    const int qt  = bid & 15;
    const int qbase = qt * BQ;
    // 4 owned q-rows: rowtile0 = {r0, r1}, rowtile1 = {r2, r3}
    int qr[4];
    #pragma unroll
    for (int r4 = 0; r4 < 4; r4++) qr[r4] = qbase + 32*w + 8*r4 + g;

    if (tid < 64) vs_s[tid] = g_vsum[bh*DD + tid];

    // ---- persistent Q fragments: 2 rowtiles, bf16, pre-scaled 1/8 ----
    uint32_t Qf[2][4][4];
    {
        const float* qp0 = gq + (size_t)bh*SS_*DD;
        #pragma unroll
        for (int rt = 0; rt < 2; rt++) {
            const float* ql = qp0 + (size_t)qr[2*rt]*DD;
            const float* qh = qp0 + (size_t)qr[2*rt+1]*DD;
            #pragma unroll
            for (int c4 = 0; c4 < 4; c4++) {
                int k0 = 16*c4 + 2*t;
                Qf[rt][c4][0] = bf2(0.125f*ql[k0    ], 0.125f*ql[k0 + 1]);
                Qf[rt][c4][1] = bf2(0.125f*qh[k0    ], 0.125f*qh[k0 + 1]);
                Qf[rt][c4][2] = bf2(0.125f*ql[k0 + 8], 0.125f*ql[k0 + 9]);
                Qf[rt][c4][3] = bf2(0.125f*qh[k0 + 8], 0.125f*qh[k0 + 9]);
            }
        }
    }

    const float4* kbase4 = (const float4*)(gk + (size_t)bh*SS_*DD);
    const float4* vbase4 = (const float4*)(gv + (size_t)bh*SS_*DD);
    const uint2* mrow[4] = {
        (const uint2*)(g_mbits + (size_t)qr[0]*64),
        (const uint2*)(g_mbits + (size_t)qr[1]*64),
        (const uint2*)(g_mbits + (size_t)qr[2]*64),
        (const uint2*)(g_mbits + (size_t)qr[3]*64) };

    float A1[2][8][4], A2[2][8][4];
    #pragma unroll
    for (int rt = 0; rt < 2; rt++)
        #pragma unroll
        for (int nb = 0; nb < 8; nb++)
            #pragma unroll
            for (int j = 0; j < 4; j++) { A1[rt][nb][j] = 0.f; A2[rt][nb][j] = 0.f; }
    float lsum[4] = {0.f, 0.f, 0.f, 0.f};

    for (int kt = 0; kt < NKT; kt++) {
        __syncthreads();

        // ---- K -> bf16 smem, V -> tf32 smem ----
        #pragma unroll
        for (int i = 0; i < 8; i++) {
            int idx = tid + i*NT;          // 1024 float4 = 64x64
            int r = idx >> 4, j = idx & 15;
            float4 kf = kbase4[(size_t)kt*1024 + idx];
            uint2 kb;
            kb.x = bf2(kf.x, kf.y);
            kb.y = bf2(kf.z, kf.w);
            *(uint2*)&Khu[r*KSTRW + 2*j] = kb;
            float4 vf = vbase4[(size_t)kt*1024 + idx];
            uint4 vb;
            vb.x = to_tf32(vf.x); vb.y = to_tf32(vf.y);
            vb.z = to_tf32(vf.z); vb.w = to_tf32(vf.w);
            *(uint4*)&Vsu[r*VSTR + 4*j] = vb;
        }
        __syncthreads();

        // ---- S = (Q/8)@K^T : K fragments shared across both rowtiles ----
        #pragma unroll
        for (int nb = 0; nb < 8; nb++) {
            const uint32_t* kr = &Khu[(8*nb + g)*KSTRW];
            uint32_t kb[8];
            #pragma unroll
            for (int c4 = 0; c4 < 4; c4++) {
                kb[2*c4]   = kr[8*c4 + t];
                kb[2*c4+1] = kr[8*c4 + t + 4];
            }
            #pragma unroll
            for (int rt = 0; rt < 2; rt++) {
                float acc[4] = {0.f, 0.f, 0.f, 0.f};
                #pragma unroll
                for (int c4 = 0; c4 < 4; c4++)
                    mma16bf(acc, Qf[rt][c4], kb[2*c4], kb[2*c4+1]);
                *(float2*)&Sst[(32*w + 16*rt + g    )*SSTR + 8*nb + 2*t] =
                    make_float2(acc[0], acc[1]);
                *(float2*)&Sst[(32*w + 16*rt + g + 8)*SSTR + 8*nb + 2*t] =
                    make_float2(acc[2], acc[3]);
            }
        }
        __syncwarp();

        // ---- PV: V fragments shared across 2 rowtiles x {A1,A2} ----
        uint2 mw[4];
        #pragma unroll
        for (int r4 = 0; r4 < 4; r4++) mw[r4] = mrow[r4][kt];

        #pragma unroll
        for (int c = 0; c < 8; c++) {
            const int klo = 8*c + t, khi = klo + 4;
            float sA[4], sB[4];
            #pragma unroll
            for (int r4 = 0; r4 < 4; r4++) {
                int row = 32*w + 8*r4 + g;
                sA[r4] = Sst[row*SSTR + klo];
                sB[r4] = Sst[row*SSTR + khi];
                lsum[r4] += __expf(sA[r4]) + __expf(sB[r4]);
            }
            uint32_t a1f[2][4], a2f[2][4];
            #pragma unroll
            for (int rt = 0; rt < 2; rt++) {
                uint32_t mA0 = mbit(mw[2*rt  ], klo), mA1 = mbit(mw[2*rt+1], klo);
                uint32_t mB0 = mbit(mw[2*rt  ], khi), mB1 = mbit(mw[2*rt+1], khi);
                a1f[rt][0] = mA0 ? to_tf32(sA[2*rt  ]) : 0u;
                a1f[rt][1] = mA1 ? to_tf32(sA[2*rt+1]) : 0u;
                a1f[rt][2] = mB0 ? to_tf32(sB[2*rt  ]) : 0u;
                a1f[rt][3] = mB1 ? to_tf32(sB[2*rt+1]) : 0u;
                a2f[rt][0] = mA0 ? 0x3f800000u : 0u;
                a2f[rt][1] = mA1 ? 0x3f800000u : 0u;
                a2f[rt][2] = mB0 ? 0x3f800000u : 0u;
                a2f[rt][3] = mB1 ? 0x3f800000u : 0u;
            }
            #pragma unroll
            for (int nb = 0; nb < 8; nb++) {
                uint32_t b0 = Vsu[klo*VSTR + 8*nb + g];
                uint32_t b1 = Vsu[khi*VSTR + 8*nb + g];
                mma8(A1[0][nb], a1f[0], b0, b1);
                mma8(A2[0][nb], a2f[0], b0, b1);
                mma8(A1[1][nb], a1f[1], b0, b1);
                mma8(A2[1][nb], a2f[1], b0, b1);
            }
        }
    }

    // ---- lse reduce within each 4-lane group ----
    #pragma unroll
    for (int r4 = 0; r4 < 4; r4++) {
        lsum[r4] += __shfl_xor_sync(0xffffffffu, lsum[r4], 1);
        lsum[r4] += __shfl_xor_sync(0xffffffffu, lsum[r4], 2);
    }

    // ---- epilogue ----
    __syncthreads();
    const int b = bh >> 4, h = bh & 15;
    #pragma unroll
    for (int rt = 0; rt < 2; rt++) {
        float lse0 = __logf(lsum[2*rt]);
        float lse1 = __logf(lsum[2*rt+1]);
        float* o0 = gout + ((size_t)b*SS_ + qr[2*rt  ])*(HH*DD) + h*DD;
        float* o1 = gout + ((size_t)b*SS_ + qr[2*rt+1])*(HH*DD) + h*DD;
        #pragma unroll
        for (int nb = 0; nb < 8; nb++) {
            int d = 8*nb + 2*t;
            float vs0 = vs_s[d], vs1 = vs_s[d + 1];
            float r00 = (A1[rt][nb][0] - lse0*A2[rt][nb][0]) - 1e9f*(vs0 - A2[rt][nb][0]);
            float r01 = (A1[rt][nb][1] - lse0*A2[rt][nb][1]) - 1e9f*(vs1 - A2[rt][nb][1]);
            float r10 = (A1[rt][nb][2] - lse1*A2[rt][nb][2]) - 1e9f*(vs0 - A2[rt][nb][2]);
            float r11 = (A1[rt][nb][3] - lse1*A2[rt][nb][3]) - 1e9f*(vs1 - A2[rt][nb][3]);
            *(float2*)&o0[d] = make_float2(r00, r01);
            *(float2*)&o1[d] = make_float2(r10, r11);
        }
    }
}

// ---------------------------------------------------------------------------
extern "C" void kernel_launch(void* const* d_in, const int* in_sizes, int n_in,
                              void* d_out, int out_size) {
    const float* q    = (const float*)d_in[0];
    const float* k    = (const float*)d_in[1];
    const float* v    = (const float*)d_in[2];
    const int*   mask = (const int*)d_in[3];
    float* out = (float*)d_out;

    const int dsm = (64*VSTR + 64*KSTRW + 128*SSTR) * 4;   // 62464 bytes
    cudaFuncSetAttribute(attn_kernel,
                         cudaFuncAttributeMaxDynamicSharedMemorySize, dsm);

    maskpack_kernel<<<(SS_*SS_)/1024, 256>>>(mask);
    vsum_kernel<<<NBH, 256>>>(v);
    attn_kernel<<<NBH*(SS_/BQ), NT, dsm>>>(q, k, v, out);
}

// round 7
// speedup vs baseline: 1.1737x; 1.1737x over previous
#include <cuda_runtime.h>
#include <cstdint>

#define BB 4
#define HH 16
#define SS_ 2048
#define DD 64
#define BQ 128
#define BK 64
#define NKT 32
#define NBH 64
#define NT 256
#define VSTRU 72   /* V smem row stride in u32 (288B): PV banks = 8t+g, perfect */
#define KSTRU 36   /* K smem row stride in u32 (144B): S banks = 4g+t, perfect */
#define SSTRU 36   /* S bf16x2 smem row stride in u32 */

__device__ float    g_vsum[NBH*DD];
__device__ uint32_t g_mbits[SS_*(SS_/32)];
__device__ uint32_t g_kbf[(size_t)NBH*SS_*(DD/2)];  /* bf16x2 pairs along d */
__device__ uint32_t g_vtf[(size_t)NBH*SS_*DD];      /* tf32-RN fp32 bits    */

// ---------------- helpers ----------------
__device__ __forceinline__ uint32_t smem_u32(const void* p) {
    uint32_t a;
    asm("{ .reg .u64 t; cvta.to.shared.u64 t, %1; cvt.u32.u64 %0, t; }"
        : "=r"(a) : "l"(p));
    return a;
}
__device__ __forceinline__ uint32_t to_tf32(float f) {
    uint32_t r; asm("cvt.rn.tf32.f32 %0, %1;" : "=r"(r) : "f"(f)); return r;
}
__device__ __forceinline__ uint32_t bf2(float lo, float hi) {
    uint32_t r; asm("cvt.rn.bf16x2.f32 %0, %1, %2;" : "=r"(r) : "f"(hi), "f"(lo));
    return r;
}
__device__ __forceinline__ void mma8(float* d, const uint32_t* a,
                                     uint32_t b0, uint32_t b1) {
    asm volatile(
        "mma.sync.aligned.m16n8k8.row.col.f32.tf32.tf32.f32 "
        "{%0,%1,%2,%3}, {%4,%5,%6,%7}, {%8,%9}, {%0,%1,%2,%3};"
        : "+f"(d[0]), "+f"(d[1]), "+f"(d[2]), "+f"(d[3])
        : "r"(a[0]), "r"(a[1]), "r"(a[2]), "r"(a[3]), "r"(b0), "r"(b1));
}
__device__ __forceinline__ void mma16bf(float* d, const uint32_t* a,
                                        uint32_t b0, uint32_t b1) {
    asm volatile(
        "mma.sync.aligned.m16n8k16.row.col.f32.bf16.bf16.f32 "
        "{%0,%1,%2,%3}, {%4,%5,%6,%7}, {%8,%9}, {%0,%1,%2,%3};"
        : "+f"(d[0]), "+f"(d[1]), "+f"(d[2]), "+f"(d[3])
        : "r"(a[0]), "r"(a[1]), "r"(a[2]), "r"(a[3]), "r"(b0), "r"(b1));
}
__device__ __forceinline__ uint32_t mbit(uint2 mw, int k) {
    return ((k < 32 ? (mw.x >> k) : (mw.y >> (k - 32))) & 1u);
}
__device__ __forceinline__ void cpa16(uint32_t sdst, const void* gsrc) {
    asm volatile("cp.async.cg.shared.global [%0], [%1], 16;"
                 :: "r"(sdst), "l"(gsrc));
}

// ---------------------------------------------------------------------------
// prep: maskpack + K->bf16x2 + V->tf32RN + vsum, fused (one launch)
// ---------------------------------------------------------------------------
__global__ void prep_kernel(const float* __restrict__ gk,
                            const float* __restrict__ gv,
                            const int*   __restrict__ gm)
{
    __shared__ float red[4][64];
    const int bid = blockIdx.x, tid = threadIdx.x;

    if (bid < 4096) {                       // mask -> bits
        int base = bid*1024 + tid;
        int a = gm[base], b = gm[base+256], c = gm[base+512], d = gm[base+768];
        unsigned ba = __ballot_sync(~0u, a != 0);
        unsigned bb = __ballot_sync(~0u, b != 0);
        unsigned bc = __ballot_sync(~0u, c != 0);
        unsigned bd = __ballot_sync(~0u, d != 0);
        if ((tid & 31) == 0) {
            g_mbits[(base      ) >> 5] = ba;
            g_mbits[(base + 256) >> 5] = bb;
            g_mbits[(base + 512) >> 5] = bc;
            g_mbits[(base + 768) >> 5] = bd;
        }
    } else if (bid < 8192) {                // K -> bf16x2 (pairs along d)
        size_t i = (size_t)(bid - 4096)*256 + tid;
        const float4* src = (const float4*)gk + i*2;
        float4 a = src[0], b = src[1];
        uint4 o;
        o.x = bf2(a.x, a.y); o.y = bf2(a.z, a.w);
        o.z = bf2(b.x, b.y); o.w = bf2(b.z, b.w);
        ((uint4*)g_kbf)[i] = o;
    } else if (bid < 16384) {               // V -> tf32-RN bits
        size_t i = (size_t)(bid - 8192)*256 + tid;
        float4 a = ((const float4*)gv)[i];
        uint4 o;
        o.x = to_tf32(a.x); o.y = to_tf32(a.y);
        o.z = to_tf32(a.z); o.w = to_tf32(a.w);
        ((uint4*)g_vtf)[i] = o;
    } else {                                // vsum (exact fp32 V)
        int bh = bid - 16384;
        int d = tid & 63, strip = tid >> 6;
        const float* vp = gv + (size_t)bh*SS_*DD;
        float a0 = 0.f, a1 = 0.f, a2 = 0.f, a3 = 0.f;
        for (int k = strip; k < SS_; k += 16) {
            a0 += vp[(k     )*DD + d];
            a1 += vp[(k +  4)*DD + d];
            a2 += vp[(k +  8)*DD + d];
            a3 += vp[(k + 12)*DD + d];
        }
        red[strip][d] = (a0 + a1) + (a2 + a3);
        __syncthreads();
        if (strip == 0)
            g_vsum[bh*DD + d] = red[0][d] + red[1][d] + red[2][d] + red[3][d];
    }
}

// ---------------------------------------------------------------------------
// main attention kernel — 8 warps x 16 q-rows, cp.async double-buffered
//   out = (A1 - lse*A2) - 1e9*(A3 - A2)
// ---------------------------------------------------------------------------
__global__ void __launch_bounds__(NT, 2)
attn_kernel(const float* __restrict__ gq, float* __restrict__ gout)
{
    extern __shared__ uint32_t smu[];
    // layout: Kbuf0, Kbuf1, Vbuf0, Vbuf1, Su
    uint32_t* Kb0 = smu;
    uint32_t* Vb0 = smu + 2*64*KSTRU;
    uint32_t* Su  = smu + 2*64*KSTRU + 2*64*VSTRU;
    __shared__ float vs_s[64];

    const uint32_t smbase = smem_u32(smu);
    const uint32_t kb_a0 = smbase;
    const uint32_t vb_a0 = smbase + 2*64*KSTRU*4;

    const int tid = threadIdx.x;
    const int w   = tid >> 5;
    const int lane = tid & 31;
    const int g = lane >> 2;
    const int t = lane & 3;
    const bool odd = (t & 1);
    const int bid = blockIdx.x;
    const int bh  = bid >> 4;
    const int qt  = bid & 15;
    const int qbase = qt * BQ;
    const int qlo = qbase + 16*w + g;
    const int qhi = qlo + 8;

    if (tid < 64) vs_s[tid] = g_vsum[bh*DD + tid];

    // ---- persistent Q fragments: bf16 pairs, pre-scaled 1/8 ----
    uint32_t Qf[4][4];
    {
        const float* ql = gq + (size_t)bh*SS_*DD + (size_t)qlo*DD;
        const float* qh = gq + (size_t)bh*SS_*DD + (size_t)qhi*DD;
        #pragma unroll
        for (int c4 = 0; c4 < 4; c4++) {
            int k0 = 16*c4 + 2*t;
            Qf[c4][0] = bf2(0.125f*ql[k0    ], 0.125f*ql[k0 + 1]);
            Qf[c4][1] = bf2(0.125f*qh[k0    ], 0.125f*qh[k0 + 1]);
            Qf[c4][2] = bf2(0.125f*ql[k0 + 8], 0.125f*ql[k0 + 9]);
            Qf[c4][3] = bf2(0.125f*qh[k0 + 8], 0.125f*qh[k0 + 9]);
        }
    }

    const char* kgb = (const char*)g_kbf + (size_t)bh*SS_*128;
    const char* vgb = (const char*)g_vtf + (size_t)bh*SS_*256;
    const uint2* mrow_lo = (const uint2*)(g_mbits + (size_t)qlo*64);
    const uint2* mrow_hi = (const uint2*)(g_mbits + (size_t)qhi*64);

    float A1[8][4], A2[8][4];
    #pragma unroll
    for (int nb = 0; nb < 8; nb++)
        #pragma unroll
        for (int j = 0; j < 4; j++) { A1[nb][j] = 0.f; A2[nb][j] = 0.f; }
    float lsum_lo = 0.f, lsum_hi = 0.f;

    // prefetch chunk coords (constant per thread)
    const int kr0 = tid >> 3,  kc0 = tid & 7;       // K: 2 chunks (i*32 rows)
    const int vr0 = tid >> 4,  vc0 = tid & 15;      // V: 4 chunks (i*16 rows)

    // ---- issue tile 0 ----
    {
        const char* kg = kgb; const char* vg = vgb;
        #pragma unroll
        for (int i = 0; i < 2; i++)
            cpa16(kb_a0 + (kr0 + 32*i)*144 + kc0*16, kg + (kr0 + 32*i)*128 + kc0*16);
        #pragma unroll
        for (int i = 0; i < 4; i++)
            cpa16(vb_a0 + (vr0 + 16*i)*288 + vc0*16, vg + (vr0 + 16*i)*256 + vc0*16);
        asm volatile("cp.async.commit_group;" ::: "memory");
    }

    for (int kt = 0; kt < NKT; kt++) {
        asm volatile("cp.async.wait_group 0;" ::: "memory");
        __syncthreads();    // tile kt visible to all; all warps done with kt-1

        // ---- issue tile kt+1 into the other buffer ----
        if (kt + 1 < NKT) {
            int nbuf = (kt + 1) & 1;
            const char* kg = kgb + (size_t)(kt+1)*BK*128;
            const char* vg = vgb + (size_t)(kt+1)*BK*256;
            uint32_t ka = kb_a0 + nbuf*64*KSTRU*4;
            uint32_t va = vb_a0 + nbuf*64*VSTRU*4;
            #pragma unroll
            for (int i = 0; i < 2; i++)
                cpa16(ka + (kr0 + 32*i)*144 + kc0*16, kg + (kr0 + 32*i)*128 + kc0*16);
            #pragma unroll
            for (int i = 0; i < 4; i++)
                cpa16(va + (vr0 + 16*i)*288 + vc0*16, vg + (vr0 + 16*i)*256 + vc0*16);
            asm volatile("cp.async.commit_group;" ::: "memory");
        }

        const uint32_t* Khu = Kb0 + (kt & 1)*64*KSTRU;
        const uint32_t* Vsu = Vb0 + (kt & 1)*64*VSTRU;

        // ---- S = (Q/8)@K^T (bf16), store bf16x2 to Su ----
        #pragma unroll
        for (int nb = 0; nb < 8; nb++) {
            float acc[4] = {0.f, 0.f, 0.f, 0.f};
            const uint32_t* kr = &Khu[(8*nb + g)*KSTRU];
            #pragma unroll
            for (int c4 = 0; c4 < 4; c4++)
                mma16bf(acc, Qf[c4], kr[8*c4 + t], kr[8*c4 + t + 4]);
            Su[(16*w + g    )*SSTRU + 4*nb + t] = bf2(acc[0], acc[1]);
            Su[(16*w + g + 8)*SSTRU + 4*nb + t] = bf2(acc[2], acc[3]);
        }
        __syncwarp();

        // ---- PV: A1 += (m*s)@V, A2 += m@V; lse fused ----
        uint2 mwlo = mrow_lo[kt];
        uint2 mwhi = mrow_hi[kt];
        #pragma unroll
        for (int c = 0; c < 8; c++) {
            const int klo = 8*c + t, khi = klo + 4;
            const int u0 = 4*c + (t >> 1), u1 = u0 + 2;
            uint32_t a0 = Su[(16*w + g    )*SSTRU + u0];
            uint32_t a1 = Su[(16*w + g + 8)*SSTRU + u0];
            uint32_t b0u = Su[(16*w + g    )*SSTRU + u1];
            uint32_t b1u = Su[(16*w + g + 8)*SSTRU + u1];
            float s0 = __uint_as_float(odd ? (a0  & 0xFFFF0000u) : (a0  << 16));
            float s1 = __uint_as_float(odd ? (a1  & 0xFFFF0000u) : (a1  << 16));
            float s2 = __uint_as_float(odd ? (b0u & 0xFFFF0000u) : (b0u << 16));
            float s3 = __uint_as_float(odd ? (b1u & 0xFFFF0000u) : (b1u << 16));
            lsum_lo += __expf(s0) + __expf(s2);
            lsum_hi += __expf(s1) + __expf(s3);
            uint32_t m0 = mbit(mwlo, klo), m1 = mbit(mwhi, klo);
            uint32_t m2 = mbit(mwlo, khi), m3 = mbit(mwhi, khi);
            uint32_t a1f[4], a2f[4];
            a1f[0] = m0 ? __float_as_uint(s0) : 0u;  a2f[0] = m0 ? 0x3f800000u : 0u;
            a1f[1] = m1 ? __float_as_uint(s1) : 0u;  a2f[1] = m1 ? 0x3f800000u : 0u;
            a1f[2] = m2 ? __float_as_uint(s2) : 0u;  a2f[2] = m2 ? 0x3f800000u : 0u;
            a1f[3] = m3 ? __float_as_uint(s3) : 0u;  a2f[3] = m3 ? 0x3f800000u : 0u;
            #pragma unroll
            for (int nb = 0; nb < 8; nb++) {
                uint32_t vb0 = Vsu[klo*VSTRU + 8*nb + g];
                uint32_t vb1 = Vsu[khi*VSTRU + 8*nb + g];
                mma8(A1[nb], a1f, vb0, vb1);
                mma8(A2[nb], a2f, vb0, vb1);
            }
        }
    }

    // ---- lse reduce within each 4-lane group ----
    lsum_lo += __shfl_xor_sync(0xffffffffu, lsum_lo, 1);
    lsum_lo += __shfl_xor_sync(0xffffffffu, lsum_lo, 2);
    lsum_hi += __shfl_xor_sync(0xffffffffu, lsum_hi, 1);
    lsum_hi += __shfl_xor_sync(0xffffffffu, lsum_hi, 2);
    const float lse_lo = __logf(lsum_lo);
    const float lse_hi = __logf(lsum_hi);

    // ---- epilogue ----
    __syncthreads();
    const int b = bh >> 4, h = bh & 15;
    float* olo = gout + ((size_t)b*SS_ + qlo)*(HH*DD) + h*DD;
    float* ohi = gout + ((size_t)b*SS_ + qhi)*(HH*DD) + h*DD;
    #pragma unroll
    for (int nb = 0; nb < 8; nb++) {
        int d = 8*nb + 2*t;
        float vs0 = vs_s[d], vs1 = vs_s[d + 1];
        float o0 = (A1[nb][0] - lse_lo*A2[nb][0]) - 1e9f*(vs0 - A2[nb][0]);
        float o1 = (A1[nb][1] - lse_lo*A2[nb][1]) - 1e9f*(vs1 - A2[nb][1]);
        float o2 = (A1[nb][2] - lse_hi*A2[nb][2]) - 1e9f*(vs0 - A2[nb][2]);
        float o3 = (A1[nb][3] - lse_hi*A2[nb][3]) - 1e9f*(vs1 - A2[nb][3]);
        *(float2*)&olo[d] = make_float2(o0, o1);
        *(float2*)&ohi[d] = make_float2(o2, o3);
    }
}

// ---------------------------------------------------------------------------
extern "C" void kernel_launch(void* const* d_in, const int* in_sizes, int n_in,
                              void* d_out, int out_size) {
    const float* q    = (const float*)d_in[0];
    const float* k    = (const float*)d_in[1];
    const float* v    = (const float*)d_in[2];
    const int*   mask = (const int*)d_in[3];
    float* out = (float*)d_out;

    const int dsm = (2*64*KSTRU + 2*64*VSTRU + 128*SSTRU) * 4;  // 73728
    cudaFuncSetAttribute(attn_kernel,
                         cudaFuncAttributeMaxDynamicSharedMemorySize, dsm);

    prep_kernel<<<16448, 256>>>(k, v, mask);
    attn_kernel<<<NBH*(SS_/BQ), NT, dsm>>>(q, out);
}

// round 8
// speedup vs baseline: 1.6291x; 1.3880x over previous
#include <cuda_runtime.h>
#include <cstdint>

#define BB 4
#define HH 16
#define SS_ 2048
#define DD 64
#define BQ 128
#define BK 64
#define NKT 32
#define NBH 64
#define NT 256
#define VSTRU 72   /* V fp16x2 smem row stride in u32: PV banks 8t+g, perfect */
#define KSTRU 36   /* K bf16x2 smem row stride in u32: S banks 4g+t, perfect */
#define KBUFU (64*KSTRU)     /* 2304 u32 */
#define VBUFU (32*VSTRU)     /* 2304 u32 */
#define STAGEU (KBUFU+VBUFU) /* 4608 u32 = 18432 B */

__device__ float    g_vsum[NBH*DD];
__device__ uint32_t g_mbits[SS_*(SS_/32)];
__device__ uint32_t g_kbf[(size_t)NBH*SS_*(DD/2)];   /* bf16x2 pairs along d */
__device__ uint32_t g_vh [(size_t)NBH*(SS_/2)*DD];   /* fp16x2 pairs along k */

// ---------------- helpers ----------------
__device__ __forceinline__ uint32_t smem_u32(const void* p) {
    uint32_t a;
    asm("{ .reg .u64 t; cvta.to.shared.u64 t, %1; cvt.u32.u64 %0, t; }"
        : "=r"(a) : "l"(p));
    return a;
}
__device__ __forceinline__ uint32_t bf2(float lo, float hi) {
    uint32_t r; asm("cvt.rn.bf16x2.f32 %0, %1, %2;" : "=r"(r) : "f"(hi), "f"(lo));
    return r;
}
__device__ __forceinline__ uint32_t h2(float lo, float hi) {
    uint32_t r; asm("cvt.rn.f16x2.f32 %0, %1, %2;" : "=r"(r) : "f"(hi), "f"(lo));
    return r;
}
__device__ __forceinline__ void mma16bf(float* d, const uint32_t* a,
                                        uint32_t b0, uint32_t b1) {
    asm volatile(
        "mma.sync.aligned.m16n8k16.row.col.f32.bf16.bf16.f32 "
        "{%0,%1,%2,%3}, {%4,%5,%6,%7}, {%8,%9}, {%0,%1,%2,%3};"
        : "+f"(d[0]), "+f"(d[1]), "+f"(d[2]), "+f"(d[3])
        : "r"(a[0]), "r"(a[1]), "r"(a[2]), "r"(a[3]), "r"(b0), "r"(b1));
}
__device__ __forceinline__ void mma16f(float* d, const uint32_t* a,
                                       uint32_t b0, uint32_t b1) {
    asm volatile(
        "mma.sync.aligned.m16n8k16.row.col.f32.f16.f16.f32 "
        "{%0,%1,%2,%3}, {%4,%5,%6,%7}, {%8,%9}, {%0,%1,%2,%3};"
        : "+f"(d[0]), "+f"(d[1]), "+f"(d[2]), "+f"(d[3])
        : "r"(a[0]), "r"(a[1]), "r"(a[2]), "r"(a[3]), "r"(b0), "r"(b1));
}
__device__ __forceinline__ uint32_t mbits2(uint2 mw, int k) {
    return ((k < 32) ? (mw.x >> k) : (mw.y >> (k - 32))) & 3u;
}
__device__ __forceinline__ uint32_t mtab(uint32_t i) {
    return ((i & 1) ? 0x0000FFFFu : 0u) | ((i & 2) ? 0xFFFF0000u : 0u);
}
__device__ __forceinline__ uint32_t ctab(uint32_t i) {
    return ((i & 1) ? 0x00003C00u : 0u) | ((i & 2) ? 0x3C000000u : 0u);
}
__device__ __forceinline__ void cpa16(uint32_t sdst, const void* gsrc) {
    asm volatile("cp.async.cg.shared.global [%0], [%1], 16;"
                 :: "r"(sdst), "l"(gsrc));
}

// ---------------------------------------------------------------------------
// prep: maskpack + K->bf16x2(d-pairs) + V->fp16x2(k-pairs) + vsum
// ---------------------------------------------------------------------------
__global__ void prep_kernel(const float* __restrict__ gk,
                            const float* __restrict__ gv,
                            const int*   __restrict__ gm)
{
    __shared__ float red[4][64];
    const int bid = blockIdx.x, tid = threadIdx.x;

    if (bid < 4096) {                       // mask -> bits
        int base = bid*1024 + tid;
        int a = gm[base], b = gm[base+256], c = gm[base+512], d = gm[base+768];
        unsigned ba = __ballot_sync(~0u, a != 0);
        unsigned bb = __ballot_sync(~0u, b != 0);
        unsigned bc = __ballot_sync(~0u, c != 0);
        unsigned bd = __ballot_sync(~0u, d != 0);
        if ((tid & 31) == 0) {
            g_mbits[(base      ) >> 5] = ba;
            g_mbits[(base + 256) >> 5] = bb;
            g_mbits[(base + 512) >> 5] = bc;
            g_mbits[(base + 768) >> 5] = bd;
        }
    } else if (bid < 8192) {                // K -> bf16x2 (pairs along d)
        size_t i = (size_t)(bid - 4096)*256 + tid;
        const float4* src = (const float4*)gk + i*2;
        float4 a = src[0], b = src[1];
        uint4 o;
        o.x = bf2(a.x, a.y); o.y = bf2(a.z, a.w);
        o.z = bf2(b.x, b.y); o.w = bf2(b.z, b.w);
        ((uint4*)g_kbf)[i] = o;
    } else if (bid < 12288) {               // V -> fp16x2 (pairs along k)
        size_t i = (size_t)(bid - 8192)*256 + tid;   // uint4 index
        size_t R = i >> 4;                  // (bh, kpair) row
        int    q = (int)(i & 15);           // float4 column within row
        const float4* v4 = (const float4*)gv;
        float4 f0 = v4[(2*R    )*16 + q];   // k = 2kp
        float4 f1 = v4[(2*R + 1)*16 + q];   // k = 2kp+1
        uint4 o;
        o.x = h2(f0.x, f1.x); o.y = h2(f0.y, f1.y);
        o.z = h2(f0.z, f1.z); o.w = h2(f0.w, f1.w);
        ((uint4*)g_vh)[i] = o;
    } else {                                // vsum (exact fp32 V)
        int bh = bid - 12288;
        int d = tid & 63, strip = tid >> 6;
        const float* vp = gv + (size_t)bh*SS_*DD;
        float a0 = 0.f, a1 = 0.f, a2 = 0.f, a3 = 0.f;
        for (int k = strip; k < SS_; k += 16) {
            a0 += vp[(k     )*DD + d];
            a1 += vp[(k +  4)*DD + d];
            a2 += vp[(k +  8)*DD + d];
            a3 += vp[(k + 12)*DD + d];
        }
        red[strip][d] = (a0 + a1) + (a2 + a3);
        __syncthreads();
        if (strip == 0)
            g_vsum[bh*DD + d] = red[0][d] + red[1][d] + red[2][d] + red[3][d];
    }
}

// ---------------------------------------------------------------------------
// main attention kernel — register-direct S->PV, fp16 PV, 3-stage cp.async
//   out = (A1 - lse*A2) - 1e9*(A3 - A2)
// ---------------------------------------------------------------------------
__global__ void __launch_bounds__(NT, 2)
attn_kernel(const float* __restrict__ gq, float* __restrict__ gout)
{
    extern __shared__ uint32_t smu[];
    __shared__ float vs_s[64];

    const uint32_t smbase = smem_u32(smu);

    const int tid = threadIdx.x;
    const int w   = tid >> 5;
    const int lane = tid & 31;
    const int g = lane >> 2;
    const int t = lane & 3;
    const int bid = blockIdx.x;
    const int bh  = bid >> 4;
    const int qt  = bid & 15;
    const int qbase = qt * BQ;
    const int qlo = qbase + 16*w + g;
    const int qhi = qlo + 8;

    if (tid < 64) vs_s[tid] = g_vsum[bh*DD + tid];

    // ---- persistent Q fragments: bf16 pairs, pre-scaled 1/8 ----
    uint32_t Qf[4][4];
    {
        const float* ql = gq + (size_t)bh*SS_*DD + (size_t)qlo*DD;
        const float* qh = gq + (size_t)bh*SS_*DD + (size_t)qhi*DD;
        #pragma unroll
        for (int c4 = 0; c4 < 4; c4++) {
            int k0 = 16*c4 + 2*t;
            Qf[c4][0] = bf2(0.125f*ql[k0    ], 0.125f*ql[k0 + 1]);
            Qf[c4][1] = bf2(0.125f*qh[k0    ], 0.125f*qh[k0 + 1]);
            Qf[c4][2] = bf2(0.125f*ql[k0 + 8], 0.125f*ql[k0 + 9]);
            Qf[c4][3] = bf2(0.125f*qh[k0 + 8], 0.125f*qh[k0 + 9]);
        }
    }

    const char* kgb = (const char*)g_kbf + (size_t)bh*SS_*128;    // 128B/k-row
    const char* vgb = (const char*)g_vh  + (size_t)bh*(SS_/2)*256; // 256B/kpair
    const uint2* mrow_lo = (const uint2*)(g_mbits + (size_t)qlo*64);
    const uint2* mrow_hi = (const uint2*)(g_mbits + (size_t)qhi*64);

    float A1[8][4], A2[8][4];
    #pragma unroll
    for (int nb = 0; nb < 8; nb++)
        #pragma unroll
        for (int j = 0; j < 4; j++) { A1[nb][j] = 0.f; A2[nb][j] = 0.f; }
    float lsum_lo = 0.f, lsum_hi = 0.f;

    // prefetch chunk coords
    const int kr0 = tid >> 3, kc0 = tid & 7;    // K: rows kr0, kr0+32 (8 ch/row)
    const int vr0 = tid >> 4, vc0 = tid & 15;   // V: rows vr0, vr0+16 (16 ch/row)

    // ---- prologue: issue tiles 0, 1 ----
    #pragma unroll
    for (int pt = 0; pt < 2; pt++) {
        uint32_t ka = smbase + pt*(STAGEU*4);
        uint32_t va = ka + KBUFU*4;
        const char* kg = kgb + (size_t)pt*BK*128;
        const char* vg = vgb + (size_t)pt*(BK/2)*256;
        cpa16(ka + kr0*144 + kc0*16,        kg + kr0*128 + kc0*16);
        cpa16(ka + (kr0+32)*144 + kc0*16,   kg + (kr0+32)*128 + kc0*16);
        cpa16(va + vr0*288 + vc0*16,        vg + vr0*256 + vc0*16);
        cpa16(va + (vr0+16)*288 + vc0*16,   vg + (vr0+16)*256 + vc0*16);
        asm volatile("cp.async.commit_group;" ::: "memory");
    }

    for (int kt = 0; kt < NKT; kt++) {
        asm volatile("cp.async.wait_group 1;" ::: "memory");
        __syncthreads();   // tile kt visible; all warps done with kt-1

        // ---- issue tile kt+2 ----
        if (kt + 2 < NKT) {
            int st = (kt + 2) % 3;
            uint32_t ka = smbase + st*(STAGEU*4);
            uint32_t va = ka + KBUFU*4;
            const char* kg = kgb + (size_t)(kt+2)*BK*128;
            const char* vg = vgb + (size_t)(kt+2)*(BK/2)*256;
            cpa16(ka + kr0*144 + kc0*16,       kg + kr0*128 + kc0*16);
            cpa16(ka + (kr0+32)*144 + kc0*16,  kg + (kr0+32)*128 + kc0*16);
            cpa16(va + vr0*288 + vc0*16,       vg + vr0*256 + vc0*16);
            cpa16(va + (vr0+16)*288 + vc0*16,  vg + (vr0+16)*256 + vc0*16);
            asm volatile("cp.async.commit_group;" ::: "memory");
        }

        const uint32_t* Khu = smu + (kt % 3)*STAGEU;
        const uint32_t* Vsu = Khu + KBUFU;

        uint2 mwlo = mrow_lo[kt];
        uint2 mwhi = mrow_hi[kt];

        // ---- per 16-k chunk: S-MMA pair -> registers -> lse/mask -> PV ----
        #pragma unroll
        for (int c4 = 0; c4 < 4; c4++) {
            // S n-blocks 2c4 (even: k 16c4..+7) and 2c4+1 (odd: +8..+15)
            float aE[4] = {0.f,0.f,0.f,0.f}, aO[4] = {0.f,0.f,0.f,0.f};
            const uint32_t* krE = &Khu[(16*c4 + g)*KSTRU];
            const uint32_t* krO = &Khu[(16*c4 + 8 + g)*KSTRU];
            #pragma unroll
            for (int d4 = 0; d4 < 4; d4++) {
                mma16bf(aE, Qf[d4], krE[8*d4 + t], krE[8*d4 + t + 4]);
                mma16bf(aO, Qf[d4], krO[8*d4 + t], krO[8*d4 + t + 4]);
            }
            // lse partials (pre-mask scores)
            lsum_lo += __expf(aE[0]) + __expf(aE[1]) + __expf(aO[0]) + __expf(aO[1]);
            lsum_hi += __expf(aE[2]) + __expf(aE[3]) + __expf(aO[2]) + __expf(aO[3]);
            // mask pair-bits; build fp16x2 A-fragments in registers
            const int kE = 16*c4 + 2*t, kO = kE + 8;
            uint32_t iEl = mbits2(mwlo, kE), iEh = mbits2(mwhi, kE);
            uint32_t iOl = mbits2(mwlo, kO), iOh = mbits2(mwhi, kO);
            uint32_t a1f[4], a2f[4];
            a1f[0] = h2(aE[0], aE[1]) & mtab(iEl);  a2f[0] = ctab(iEl);
            a1f[1] = h2(aE[2], aE[3]) & mtab(iEh);  a2f[1] = ctab(iEh);
            a1f[2] = h2(aO[0], aO[1]) & mtab(iOl);  a2f[2] = ctab(iOl);
            a1f[3] = h2(aO[2], aO[3]) & mtab(iOh);  a2f[3] = ctab(iOh);
            // PV: fp16 m16n8k16, V fragments shared by A1/A2
            const uint32_t* vrl = &Vsu[(8*c4 + t    )*VSTRU];
            const uint32_t* vrh = &Vsu[(8*c4 + t + 4)*VSTRU];
            #pragma unroll
            for (int nb = 0; nb < 8; nb++) {
                uint32_t b0 = vrl[8*nb + g];
                uint32_t b1 = vrh[8*nb + g];
                mma16f(A1[nb], a1f, b0, b1);
                mma16f(A2[nb], a2f, b0, b1);
            }
        }
    }

    // ---- lse reduce within each 4-lane group ----
    lsum_lo += __shfl_xor_sync(0xffffffffu, lsum_lo, 1);
    lsum_lo += __shfl_xor_sync(0xffffffffu, lsum_lo, 2);
    lsum_hi += __shfl_xor_sync(0xffffffffu, lsum_hi, 1);
    lsum_hi += __shfl_xor_sync(0xffffffffu, lsum_hi, 2);
    const float lse_lo = __logf(lsum_lo);
    const float lse_hi = __logf(lsum_hi);

    // ---- epilogue: out = (A1 - lse*A2) - 1e9*(vs - A2) ----
    __syncthreads();
    const int b = bh >> 4, h = bh & 15;
    float* olo = gout + ((size_t)b*SS_ + qlo)*(HH*DD) + h*DD;
    float* ohi = gout + ((size_t)b*SS_ + qhi)*(HH*DD) + h*DD;
    #pragma unroll
    for (int nb = 0; nb < 8; nb++) {
        int d = 8*nb + 2*t;
        float vs0 = vs_s[d], vs1 = vs_s[d + 1];
        float o0 = (A1[nb][0] - lse_lo*A2[nb][0]) - 1e9f*(vs0 - A2[nb][0]);
        float o1 = (A1[nb][1] - lse_lo*A2[nb][1]) - 1e9f*(vs1 - A2[nb][1]);
        float o2 = (A1[nb][2] - lse_hi*A2[nb][2]) - 1e9f*(vs0 - A2[nb][2]);
        float o3 = (A1[nb][3] - lse_hi*A2[nb][3]) - 1e9f*(vs1 - A2[nb][3]);
        *(float2*)&olo[d] = make_float2(o0, o1);
        *(float2*)&ohi[d] = make_float2(o2, o3);
    }
}

// ---------------------------------------------------------------------------
extern "C" void kernel_launch(void* const* d_in, const int* in_sizes, int n_in,
                              void* d_out, int out_size) {
    const float* q    = (const float*)d_in[0];
    const float* k    = (const float*)d_in[1];
    const float* v    = (const float*)d_in[2];
    const int*   mask = (const int*)d_in[3];
    float* out = (float*)d_out;

    const int dsm = 3*STAGEU*4;   // 55296 bytes
    cudaFuncSetAttribute(attn_kernel,
                         cudaFuncAttributeMaxDynamicSharedMemorySize, dsm);

    prep_kernel<<<12352, 256>>>(k, v, mask);
    attn_kernel<<<NBH*(SS_/BQ), NT, dsm>>>(q, out);
}

// round 9
// speedup vs baseline: 1.9233x; 1.1806x over previous
#include <cuda_runtime.h>
#include <cuda_fp16.h>
#include <cstdint>

#define BB 4
#define HH 16
#define SS_ 2048
#define DD 64
#define BQ 128
#define BK 64
#define NKT 32
#define NBH 64
#define NT 256
#define VSTRU 72   /* V fp16x2 smem row stride in u32: PV banks 8t+g, perfect */
#define KSTRU 36   /* K bf16x2 smem row stride in u32: S banks 4g+t, perfect */
#define KBUFU (64*KSTRU)     /* 2304 u32 */
#define VBUFU (32*VSTRU)     /* 2304 u32 */
#define STAGEU (KBUFU+VBUFU) /* 4608 u32 = 18432 B */
#define LOG2E 1.4426950408889634f
#define LN2   0.6931471805599453f

__device__ float    g_vsum[NBH*DD];
__device__ uint32_t g_kbf[(size_t)NBH*SS_*(DD/2)];   /* bf16x2 pairs along d */
__device__ uint32_t g_vh [(size_t)NBH*(SS_/2)*DD];   /* fp16x2 pairs along k */
__device__ uint4    g_mfrag[524288];                 /* per-thread mask AND-frags, 8 MB */

// ---------------- helpers ----------------
__device__ __forceinline__ uint32_t smem_u32(const void* p) {
    uint32_t a;
    asm("{ .reg .u64 t; cvta.to.shared.u64 t, %1; cvt.u32.u64 %0, t; }"
        : "=r"(a) : "l"(p));
    return a;
}
__device__ __forceinline__ uint32_t bf2(float lo, float hi) {
    uint32_t r; asm("cvt.rn.bf16x2.f32 %0, %1, %2;" : "=r"(r) : "f"(hi), "f"(lo));
    return r;
}
__device__ __forceinline__ uint32_t h2(float lo, float hi) {
    uint32_t r; asm("cvt.rn.f16x2.f32 %0, %1, %2;" : "=r"(r) : "f"(hi), "f"(lo));
    return r;
}
__device__ __forceinline__ uint32_t ex2h2(uint32_t a) {
    uint32_t d; asm("ex2.approx.f16x2 %0, %1;" : "=r"(d) : "r"(a)); return d;
}
__device__ __forceinline__ uint32_t hadd2u(uint32_t a, uint32_t b) {
    uint32_t d; asm("add.rn.f16x2 %0, %1, %2;" : "=r"(d) : "r"(a), "r"(b)); return d;
}
__device__ __forceinline__ void mma16bf(float* d, const uint32_t* a,
                                        uint32_t b0, uint32_t b1) {
    asm volatile(
        "mma.sync.aligned.m16n8k16.row.col.f32.bf16.bf16.f32 "
        "{%0,%1,%2,%3}, {%4,%5,%6,%7}, {%8,%9}, {%0,%1,%2,%3};"
        : "+f"(d[0]), "+f"(d[1]), "+f"(d[2]), "+f"(d[3])
        : "r"(a[0]), "r"(a[1]), "r"(a[2]), "r"(a[3]), "r"(b0), "r"(b1));
}
__device__ __forceinline__ void mma16f(float* d, const uint32_t* a,
                                       uint32_t b0, uint32_t b1) {
    asm volatile(
        "mma.sync.aligned.m16n8k16.row.col.f32.f16.f16.f32 "
        "{%0,%1,%2,%3}, {%4,%5,%6,%7}, {%8,%9}, {%0,%1,%2,%3};"
        : "+f"(d[0]), "+f"(d[1]), "+f"(d[2]), "+f"(d[3])
        : "r"(a[0]), "r"(a[1]), "r"(a[2]), "r"(a[3]), "r"(b0), "r"(b1));
}
__device__ __forceinline__ void cpa16(uint32_t sdst, const void* gsrc) {
    asm volatile("cp.async.cg.shared.global [%0], [%1], 16;"
                 :: "r"(sdst), "l"(gsrc));
}

// ---------------------------------------------------------------------------
// prep: mask-fragments + K->bf16x2 + V->fp16x2(k-pairs) + vsum
// ---------------------------------------------------------------------------
__global__ void prep_kernel(const float* __restrict__ gk,
                            const float* __restrict__ gv,
                            const int*   __restrict__ gm)
{
    __shared__ float red[4][64];
    const int bid = blockIdx.x, tid = threadIdx.x;

    if (bid < 2048) {                       // mask AND-fragments
        int i  = bid*256 + tid;             // 0..524287
        int t  = i & 3;
        int g  = (i >> 2) & 7;
        int c4 = (i >> 5) & 3;
        int kt = (i >> 7) & 31;
        int pp = i >> 12;                   // 0..127
        int qlo = pp*16 + g, qhi = qlo + 8;
        int kE  = kt*64 + 16*c4 + 2*t, kO = kE + 8;
        const int* ml = gm + (size_t)qlo*SS_;
        const int* mh = gm + (size_t)qhi*SS_;
        uint4 o;
        o.x = (ml[kE]   ? 0xFFFFu : 0u) | (ml[kE+1] ? 0xFFFF0000u : 0u);
        o.y = (mh[kE]   ? 0xFFFFu : 0u) | (mh[kE+1] ? 0xFFFF0000u : 0u);
        o.z = (ml[kO]   ? 0xFFFFu : 0u) | (ml[kO+1] ? 0xFFFF0000u : 0u);
        o.w = (mh[kO]   ? 0xFFFFu : 0u) | (mh[kO+1] ? 0xFFFF0000u : 0u);
        g_mfrag[i] = o;
    } else if (bid < 6144) {                // K -> bf16x2 (pairs along d)
        size_t i = (size_t)(bid - 2048)*256 + tid;
        const float4* src = (const float4*)gk + i*2;
        float4 a = src[0], b = src[1];
        uint4 o;
        o.x = bf2(a.x, a.y); o.y = bf2(a.z, a.w);
        o.z = bf2(b.x, b.y); o.w = bf2(b.z, b.w);
        ((uint4*)g_kbf)[i] = o;
    } else if (bid < 10240) {               // V -> fp16x2 (pairs along k)
        size_t i = (size_t)(bid - 6144)*256 + tid;   // uint4 index
        size_t R = i >> 4;
        int    q = (int)(i & 15);
        const float4* v4 = (const float4*)gv;
        float4 f0 = v4[(2*R    )*16 + q];
        float4 f1 = v4[(2*R + 1)*16 + q];
        uint4 o;
        o.x = h2(f0.x, f1.x); o.y = h2(f0.y, f1.y);
        o.z = h2(f0.z, f1.z); o.w = h2(f0.w, f1.w);
        ((uint4*)g_vh)[i] = o;
    } else {                                // vsum (exact fp32 V)
        int bh = bid - 10240;
        int d = tid & 63, strip = tid >> 6;
        const float* vp = gv + (size_t)bh*SS_*DD;
        float a0 = 0.f, a1 = 0.f, a2 = 0.f, a3 = 0.f;
        for (int k = strip; k < SS_; k += 16) {
            a0 += vp[(k     )*DD + d];
            a1 += vp[(k +  4)*DD + d];
            a2 += vp[(k +  8)*DD + d];
            a3 += vp[(k + 12)*DD + d];
        }
        red[strip][d] = (a0 + a1) + (a2 + a3);
        __syncthreads();
        if (strip == 0)
            g_vsum[bh*DD + d] = red[0][d] + red[1][d] + red[2][d] + red[3][d];
    }
}

// ---------------------------------------------------------------------------
// main attention kernel — fp16x2 exp, precomputed mask frags
//   out = (ln2*A1 - lse*A2) - 1e9*(A3 - A2);  S-mma emits s*log2e
// ---------------------------------------------------------------------------
__global__ void __launch_bounds__(NT, 2)
attn_kernel(const float* __restrict__ gq, float* __restrict__ gout)
{
    extern __shared__ uint32_t smu[];
    __shared__ float vs_s[64];

    const uint32_t smbase = smem_u32(smu);

    const int tid = threadIdx.x;
    const int w   = tid >> 5;
    const int lane = tid & 31;
    const int g = lane >> 2;
    const int t = lane & 3;
    const int bid = blockIdx.x;
    const int bh  = bid >> 4;
    const int qt  = bid & 15;
    const int qbase = qt * BQ;
    const int qlo = qbase + 16*w + g;
    const int qhi = qlo + 8;

    if (tid < 64) vs_s[tid] = g_vsum[bh*DD + tid];

    // ---- persistent Q fragments: bf16 pairs, pre-scaled by log2e/8 ----
    uint32_t Qf[4][4];
    {
        const float qs = 0.125f * LOG2E;
        const float* ql = gq + (size_t)bh*SS_*DD + (size_t)qlo*DD;
        const float* qh = gq + (size_t)bh*SS_*DD + (size_t)qhi*DD;
        #pragma unroll
        for (int c4 = 0; c4 < 4; c4++) {
            int k0 = 16*c4 + 2*t;
            Qf[c4][0] = bf2(qs*ql[k0    ], qs*ql[k0 + 1]);
            Qf[c4][1] = bf2(qs*qh[k0    ], qs*qh[k0 + 1]);
            Qf[c4][2] = bf2(qs*ql[k0 + 8], qs*ql[k0 + 9]);
            Qf[c4][3] = bf2(qs*qh[k0 + 8], qs*qh[k0 + 9]);
        }
    }

    const char* kgb = (const char*)g_kbf + (size_t)bh*SS_*128;
    const char* vgb = (const char*)g_vh  + (size_t)bh*(SS_/2)*256;
    // mask fragment base: pp = qt*8 + w; element (((pp*32+kt)*4+c4)*32+lane)
    const uint4* mfb = g_mfrag + (((size_t)(qt*8 + w)*32)*4)*32 + lane;

    float A1[8][4], A2[8][4];
    #pragma unroll
    for (int nb = 0; nb < 8; nb++)
        #pragma unroll
        for (int j = 0; j < 4; j++) { A1[nb][j] = 0.f; A2[nb][j] = 0.f; }
    uint32_t lsum2_lo = 0u, lsum2_hi = 0u;   // fp16x2 partial exp-sums

    const int kr0 = tid >> 3, kc0 = tid & 7;
    const int vr0 = tid >> 4, vc0 = tid & 15;

    // ---- prologue: issue tiles 0, 1 ----
    #pragma unroll
    for (int pt = 0; pt < 2; pt++) {
        uint32_t ka = smbase + pt*(STAGEU*4);
        uint32_t va = ka + KBUFU*4;
        const char* kg = kgb + (size_t)pt*BK*128;
        const char* vg = vgb + (size_t)pt*(BK/2)*256;
        cpa16(ka + kr0*144 + kc0*16,        kg + kr0*128 + kc0*16);
        cpa16(ka + (kr0+32)*144 + kc0*16,   kg + (kr0+32)*128 + kc0*16);
        cpa16(va + vr0*288 + vc0*16,        vg + vr0*256 + vc0*16);
        cpa16(va + (vr0+16)*288 + vc0*16,   vg + (vr0+16)*256 + vc0*16);
        asm volatile("cp.async.commit_group;" ::: "memory");
    }

    for (int kt = 0; kt < NKT; kt++) {
        asm volatile("cp.async.wait_group 1;" ::: "memory");
        __syncthreads();

        // ---- mask fragments for this tile (L2-resident, 64x bh reuse) ----
        const uint4* mfp = mfb + (size_t)kt*128;
        uint4 am[4];
        am[0] = mfp[0]; am[1] = mfp[32]; am[2] = mfp[64]; am[3] = mfp[96];

        // ---- issue tile kt+2 ----
        if (kt + 2 < NKT) {
            int st = (kt + 2) % 3;
            uint32_t ka = smbase + st*(STAGEU*4);
            uint32_t va = ka + KBUFU*4;
            const char* kg = kgb + (size_t)(kt+2)*BK*128;
            const char* vg = vgb + (size_t)(kt+2)*(BK/2)*256;
            cpa16(ka + kr0*144 + kc0*16,       kg + kr0*128 + kc0*16);
            cpa16(ka + (kr0+32)*144 + kc0*16,  kg + (kr0+32)*128 + kc0*16);
            cpa16(va + vr0*288 + vc0*16,       vg + vr0*256 + vc0*16);
            cpa16(va + (vr0+16)*288 + vc0*16,  vg + (vr0+16)*256 + vc0*16);
            asm volatile("cp.async.commit_group;" ::: "memory");
        }

        const uint32_t* Khu = smu + (kt % 3)*STAGEU;
        const uint32_t* Vsu = Khu + KBUFU;

        // ---- per 16-k chunk: S-MMA -> regs -> ex2.f16x2 + mask -> PV ----
        #pragma unroll
        for (int c4 = 0; c4 < 4; c4++) {
            float aE[4] = {0.f,0.f,0.f,0.f}, aO[4] = {0.f,0.f,0.f,0.f};
            const uint32_t* krE = &Khu[(16*c4 + g)*KSTRU];
            const uint32_t* krO = &Khu[(16*c4 + 8 + g)*KSTRU];
            #pragma unroll
            for (int d4 = 0; d4 < 4; d4++) {
                mma16bf(aE, Qf[d4], krE[8*d4 + t], krE[8*d4 + t + 4]);
                mma16bf(aO, Qf[d4], krO[8*d4 + t], krO[8*d4 + t + 4]);
            }
            // fp16 pairs of s*log2e: feed both ex2 (lse) and a1f
            uint32_t hEl = h2(aE[0], aE[1]), hEh = h2(aE[2], aE[3]);
            uint32_t hOl = h2(aO[0], aO[1]), hOh = h2(aO[2], aO[3]);
            lsum2_lo = hadd2u(lsum2_lo, hadd2u(ex2h2(hEl), ex2h2(hOl)));
            lsum2_hi = hadd2u(lsum2_hi, hadd2u(ex2h2(hEh), ex2h2(hOh)));
            const uint4 amc = am[c4];
            uint32_t a1f[4], a2f[4];
            a1f[0] = hEl & amc.x;  a2f[0] = amc.x & 0x3C003C00u;
            a1f[1] = hEh & amc.y;  a2f[1] = amc.y & 0x3C003C00u;
            a1f[2] = hOl & amc.z;  a2f[2] = amc.z & 0x3C003C00u;
            a1f[3] = hOh & amc.w;  a2f[3] = amc.w & 0x3C003C00u;
            // PV: fp16 m16n8k16, V fragments shared by A1/A2
            const uint32_t* vrl = &Vsu[(8*c4 + t    )*VSTRU];
            const uint32_t* vrh = &Vsu[(8*c4 + t + 4)*VSTRU];
            #pragma unroll
            for (int nb = 0; nb < 8; nb++) {
                uint32_t b0 = vrl[8*nb + g];
                uint32_t b1 = vrh[8*nb + g];
                mma16f(A1[nb], a1f, b0, b1);
                mma16f(A2[nb], a2f, b0, b1);
            }
        }
    }

    // ---- lse: fp16x2 shfl-reduce over the 4 lanes of each group ----
    lsum2_lo = hadd2u(lsum2_lo, __shfl_xor_sync(0xffffffffu, lsum2_lo, 1));
    lsum2_lo = hadd2u(lsum2_lo, __shfl_xor_sync(0xffffffffu, lsum2_lo, 2));
    lsum2_hi = hadd2u(lsum2_hi, __shfl_xor_sync(0xffffffffu, lsum2_hi, 1));
    lsum2_hi = hadd2u(lsum2_hi, __shfl_xor_sync(0xffffffffu, lsum2_hi, 2));
    float2 flo = __half22float2(*(__half2*)&lsum2_lo);
    float2 fhi = __half22float2(*(__half2*)&lsum2_hi);
    const float lse_lo = __logf(flo.x + flo.y);
    const float lse_hi = __logf(fhi.x + fhi.y);

    // ---- epilogue: out = (ln2*A1 - lse*A2) - 1e9*(vs - A2) ----
    __syncthreads();
    const int b = bh >> 4, h = bh & 15;
    float* olo = gout + ((size_t)b*SS_ + qlo)*(HH*DD) + h*DD;
    float* ohi = gout + ((size_t)b*SS_ + qhi)*(HH*DD) + h*DD;
    #pragma unroll
    for (int nb = 0; nb < 8; nb++) {
        int d = 8*nb + 2*t;
        float vs0 = vs_s[d], vs1 = vs_s[d + 1];
        float o0 = (LN2*A1[nb][0] - lse_lo*A2[nb][0]) - 1e9f*(vs0 - A2[nb][0]);
        float o1 = (LN2*A1[nb][1] - lse_lo*A2[nb][1]) - 1e9f*(vs1 - A2[nb][1]);
        float o2 = (LN2*A1[nb][2] - lse_hi*A2[nb][2]) - 1e9f*(vs0 - A2[nb][2]);
        float o3 = (LN2*A1[nb][3] - lse_hi*A2[nb][3]) - 1e9f*(vs1 - A2[nb][3]);
        *(float2*)&olo[d] = make_float2(o0, o1);
        *(float2*)&ohi[d] = make_float2(o2, o3);
    }
}

// ---------------------------------------------------------------------------
extern "C" void kernel_launch(void* const* d_in, const int* in_sizes, int n_in,
                              void* d_out, int out_size) {
    const float* q    = (const float*)d_in[0];
    const float* k    = (const float*)d_in[1];
    const float* v    = (const float*)d_in[2];
    const int*   mask = (const int*)d_in[3];
    float* out = (float*)d_out;

    const int dsm = 3*STAGEU*4;   // 55296 bytes
    cudaFuncSetAttribute(attn_kernel,
                         cudaFuncAttributeMaxDynamicSharedMemorySize, dsm);

    prep_kernel<<<10304, 256>>>(k, v, mask);
    attn_kernel<<<NBH*(SS_/BQ), NT, dsm>>>(q, out);
}